// round 1
// baseline (speedup 1.0000x reference)
#include <cuda_runtime.h>
#include <math.h>

#define T_STEPS 512
#define BATCH   32
#define D_DIM   1024
#define N_DIM   1024
#define R_DIM   8
#define M_ROWS  (T_STEPS*BATCH)   /* 16384 */
#define EPSV    1e-6f

// ---------------- scratch (static device allocations; no cudaMalloc) -------
__device__ float g_k[M_ROWS * N_DIM];      // 64 MB
__device__ float g_v[M_ROWS * N_DIM];      // 64 MB
__device__ float g_q[M_ROWS * N_DIM];      // 64 MB
__device__ float g_coef[M_ROWS * 24];      // 1.5 MB  [t][b][24]: 0-7 Vtk,8-15 kr,16-23 Vtq

// ---------------- fast, accurate transcendentals ---------------------------
__device__ __forceinline__ float tanh_fast(float x) {
    // exp2-based: rel error ~1e-7, unlike tanh.approx (abs err ~5e-4).
    x = fminf(15.f, fmaxf(-15.f, x));
    float e = __expf(2.f * x);
    return __fdividef(e - 1.f, e + 1.f);
}
__device__ __forceinline__ float out_silu(float s) {
    // s * silu(s) = s^2 * sigmoid(s)
    float xs = fminf(30.f, fmaxf(-30.f, s));
    float e  = __expf(-xs);
    float sig = __fdividef(1.f, 1.f + e);
    return s * s * sig;
}

// ============================================================================
// Phase A: C[m,n] = sum_k A[m,k] * W[n,k]  for W in {Wk,Wv,Wq} (z-indexed).
// Classic 128x128x8 fp32 SIMT tile, 256 threads, 8x8 per-thread microtile.
// ============================================================================
__global__ __launch_bounds__(256, 2) void gemm3_kernel(
    const float* __restrict__ A,
    const float* __restrict__ Wk, const float* __restrict__ Wv,
    const float* __restrict__ Wq)
{
    const int K = D_DIM;
    const float* W = (blockIdx.z == 0) ? Wk : (blockIdx.z == 1) ? Wv : Wq;
    float* C = (blockIdx.z == 0) ? g_k : (blockIdx.z == 1) ? g_v : g_q;

    __shared__ float As[8][132];
    __shared__ float Bs[8][132];

    const int tid = threadIdx.x;
    const int row = tid >> 1;            // 0..127
    const int qd  = (tid & 1) * 4;       // 0 or 4
    const int by = blockIdx.y, bx = blockIdx.x;
    const int ty = tid >> 4;             // 0..15 (m-group)
    const int tx = tid & 15;             // 0..15 (n-group)

    const float* Ag = A + (size_t)(by * 128 + row) * K + qd;
    const float* Wg = W + (size_t)(bx * 128 + row) * K + qd;

    float acc[8][8];
#pragma unroll
    for (int i = 0; i < 8; i++)
#pragma unroll
        for (int j = 0; j < 8; j++) acc[i][j] = 0.f;

    float4 a4 = *(const float4*)Ag;
    float4 w4 = *(const float4*)Wg;

    for (int kt = 0; kt < K / 8; ++kt) {
        As[qd + 0][row] = a4.x; As[qd + 1][row] = a4.y;
        As[qd + 2][row] = a4.z; As[qd + 3][row] = a4.w;
        Bs[qd + 0][row] = w4.x; Bs[qd + 1][row] = w4.y;
        Bs[qd + 2][row] = w4.z; Bs[qd + 3][row] = w4.w;
        __syncthreads();

        if (kt < K / 8 - 1) {
            a4 = *(const float4*)(Ag + (kt + 1) * 8);
            w4 = *(const float4*)(Wg + (kt + 1) * 8);
        }

#pragma unroll
        for (int k = 0; k < 8; k++) {
            float4 a0 = *(const float4*)&As[k][ty * 8];
            float4 a1 = *(const float4*)&As[k][ty * 8 + 4];
            float4 b0 = *(const float4*)&Bs[k][tx * 8];
            float4 b1 = *(const float4*)&Bs[k][tx * 8 + 4];
            float ra[8] = {a0.x, a0.y, a0.z, a0.w, a1.x, a1.y, a1.z, a1.w};
            float rb[8] = {b0.x, b0.y, b0.z, b0.w, b1.x, b1.y, b1.z, b1.w};
#pragma unroll
            for (int i = 0; i < 8; i++)
#pragma unroll
                for (int j = 0; j < 8; j++)
                    acc[i][j] = fmaf(ra[i], rb[j], acc[i][j]);
        }
        __syncthreads();
    }

    float* Cb = C + (size_t)(by * 128 + ty * 8) * N_DIM + bx * 128 + tx * 8;
#pragma unroll
    for (int i = 0; i < 8; i++) {
        *(float4*)&Cb[(size_t)i * N_DIM]     = make_float4(acc[i][0], acc[i][1], acc[i][2], acc[i][3]);
        *(float4*)&Cb[(size_t)i * N_DIM + 4] = make_float4(acc[i][4], acc[i][5], acc[i][6], acc[i][7]);
    }
}

// ============================================================================
// Phase B: per (t,b) compute 24 coefficients:
//   normsq = ||k_t||^2 ; scale = 1/(sqrt(normsq)+eps)
//   Vtk[j] = scale * sum_i V[b,i,j]*k[i]
//   kr[j]  = scale * sum_i Wkr[j,i]*k[i]
//   Vtq[j] =         sum_i V[b,i,j]*q[i]
// One block handles (b, 16 consecutive t). V,Wkr register-resident per thread.
// ============================================================================
__global__ __launch_bounds__(256) void coef_kernel(
    const float* __restrict__ V0, const float* __restrict__ Wkr)
{
    __shared__ float sred[8 * 25];
    __shared__ float sfin[25];

    const int b  = blockIdx.y;
    const int t0 = blockIdx.x * 16;
    const int tid = threadIdx.x;
    const int lane = tid & 31, warp = tid >> 5;

    float Vreg[4][8], Wreg[4][8];
#pragma unroll
    for (int ii = 0; ii < 4; ii++) {
        int i = tid + ii * 256;
        const float4* vp = (const float4*)&V0[(size_t)b * N_DIM * 8 + (size_t)i * 8];
        float4 v0 = vp[0], v1 = vp[1];
        Vreg[ii][0] = v0.x; Vreg[ii][1] = v0.y; Vreg[ii][2] = v0.z; Vreg[ii][3] = v0.w;
        Vreg[ii][4] = v1.x; Vreg[ii][5] = v1.y; Vreg[ii][6] = v1.z; Vreg[ii][7] = v1.w;
#pragma unroll
        for (int j = 0; j < 8; j++) Wreg[ii][j] = Wkr[j * N_DIM + i];
    }

    for (int tt = 0; tt < 16; tt++) {
        const int t = t0 + tt;
        const float* krow = &g_k[(size_t)(t * BATCH + b) * N_DIM];
        const float* qrow = &g_q[(size_t)(t * BATCH + b) * N_DIM];

        float acc[25];
#pragma unroll
        for (int c = 0; c < 25; c++) acc[c] = 0.f;

#pragma unroll
        for (int ii = 0; ii < 4; ii++) {
            int i = tid + ii * 256;
            float kv = krow[i];
            float qv = qrow[i];
            acc[24] = fmaf(kv, kv, acc[24]);
#pragma unroll
            for (int j = 0; j < 8; j++) {
                float vv = Vreg[ii][j];
                acc[j]      = fmaf(vv, kv, acc[j]);
                acc[16 + j] = fmaf(vv, qv, acc[16 + j]);
                acc[8 + j]  = fmaf(Wreg[ii][j], kv, acc[8 + j]);
            }
        }
#pragma unroll
        for (int off = 16; off > 0; off >>= 1)
#pragma unroll
            for (int c = 0; c < 25; c++)
                acc[c] += __shfl_down_sync(0xffffffffu, acc[c], off);

        if (lane == 0) {
#pragma unroll
            for (int c = 0; c < 25; c++) sred[warp * 25 + c] = acc[c];
        }
        __syncthreads();
        if (tid < 25) {
            float s = 0.f;
#pragma unroll
            for (int w = 0; w < 8; w++) s += sred[w * 25 + tid];
            sfin[tid] = s;
        }
        __syncthreads();
        if (tid < 24) {
            float scale = (tid < 16) ? (1.0f / (sqrtf(sfin[24]) + EPSV)) : 1.0f;
            g_coef[(size_t)(t * BATCH + b) * 24 + tid] = sfin[tid] * scale;
        }
        __syncthreads();
    }
}

// ============================================================================
// Phase C: the scan. Thread (b,i) keeps U[b,i,0..7] in registers.
// Per step: 24 broadcast coefficients from smem, 1 coalesced v load, ~24 FMA,
// 8 tanh, 1 sigmoid, 1 store. Zero inter-thread communication.
// ============================================================================
__global__ __launch_bounds__(256) void scan_kernel(
    const float* __restrict__ U0, float* __restrict__ out, int writeExtra)
{
    const int CH = 64;
    __shared__ float sc[CH * 24];

    const int b   = blockIdx.y;
    const int i   = blockIdx.x * 256 + threadIdx.x;
    const int tid = threadIdx.x;

    float U[8];
    {
        const float4* up = (const float4*)&U0[((size_t)b * N_DIM + i) * 8];
        float4 u0 = up[0], u1 = up[1];
        U[0]=u0.x; U[1]=u0.y; U[2]=u0.z; U[3]=u0.w;
        U[4]=u1.x; U[5]=u1.y; U[6]=u1.z; U[7]=u1.w;
    }

    float vcur = g_v[(size_t)b * N_DIM + i];   // t = 0

    for (int tc = 0; tc < T_STEPS; tc += CH) {
        __syncthreads();
        for (int idx = tid; idx < CH * 24; idx += 256) {
            int tt = idx / 24, c = idx - tt * 24;
            sc[idx] = g_coef[(size_t)((tc + tt) * BATCH + b) * 24 + c];
        }
        __syncthreads();

#pragma unroll 2
        for (int tt = 0; tt < CH; tt++) {
            const int t = tc + tt;
            float vnext = (t + 1 < T_STEPS)
                        ? g_v[(size_t)((t + 1) * BATCH + b) * N_DIM + i] : 0.f;
            const float* c = &sc[tt * 24];

            float ret = U[0]*c[0];
#pragma unroll
            for (int j = 1; j < 8; j++) ret = fmaf(U[j], c[j], ret);
            float delta = vcur - ret;

#pragma unroll
            for (int j = 0; j < 8; j++)
                U[j] = tanh_fast(fmaf(delta, c[8 + j], U[j]));

            float sq = U[0]*c[16];
#pragma unroll
            for (int j = 1; j < 8; j++) sq = fmaf(U[j], c[16 + j], sq);

            out[(size_t)(t * BATCH + b) * N_DIM + i] = out_silu(sq);
            vcur = vnext;
        }
    }

    if (writeExtra) {
        float* uf = out + (size_t)M_ROWS * N_DIM + ((size_t)b * N_DIM + i) * 8;
        ((float4*)uf)[0] = make_float4(U[0], U[1], U[2], U[3]);
        ((float4*)uf)[1] = make_float4(U[4], U[5], U[6], U[7]);
    }
}

// ============================================================================
extern "C" void kernel_launch(void* const* d_in, const int* in_sizes, int n_in,
                              void* d_out, int out_size)
{
    const float* x   = (const float*)d_in[0];
    const float* Wk  = (const float*)d_in[1];
    const float* Wv  = (const float*)d_in[2];
    const float* Wq  = (const float*)d_in[3];
    const float* Wkr = (const float*)d_in[4];
    const float* U0  = (const float*)d_in[5];
    const float* V0  = (const float*)d_in[6];
    float* out = (float*)d_out;

    (void)in_sizes; (void)n_in;

    // Phase A: k,v,q projections
    gemm3_kernel<<<dim3(N_DIM / 128, M_ROWS / 128, 3), 256>>>(x, Wk, Wv, Wq);

    // Phase B: per-(t,b) coefficient reductions
    coef_kernel<<<dim3(T_STEPS / 16, BATCH), 256>>>(V0, Wkr);

    // Phase C: register-resident scan
    const int extraElems = 2 * BATCH * N_DIM * R_DIM;
    int writeExtra = (out_size >= M_ROWS * N_DIM + extraElems) ? 1 : 0;
    scan_kernel<<<dim3(N_DIM / 256, BATCH), 256>>>(U0, out, writeExtra);

    // V is returned unchanged by the reference; append it if out buffer holds it.
    if (writeExtra) {
        cudaMemcpyAsync(out + (size_t)M_ROWS * N_DIM + BATCH * N_DIM * R_DIM,
                        V0, (size_t)BATCH * N_DIM * R_DIM * sizeof(float),
                        cudaMemcpyDeviceToDevice, 0);
    }
}

// round 3
// speedup vs baseline: 2.4359x; 2.4359x over previous
#include <cuda_runtime.h>
#include <cuda_bf16.h>
#include <math.h>
#include <stdint.h>

#define T_STEPS 512
#define BATCH   32
#define D_DIM   1024
#define N_DIM   1024
#define R_DIM   8
#define M_ROWS  (T_STEPS*BATCH)   /* 16384 */
#define EPSV    1e-6f

// GEMM tiling
#define GMT 128                  /* M tile */
#define GNT 128                  /* N tile */
#define KC  64                   /* K chunk */
#define NSTEP (D_DIM/KC)         /* 16 */
#define STAGE_BYTES 65536        /* Ahi16K + Alo16K + Bhi16K + Blo16K */
#define SMEM_BYTES  (2*STAGE_BYTES)

// ---------------- scratch (static device allocations; no cudaMalloc) -------
__device__ float g_k[M_ROWS * N_DIM];      // 64 MB
__device__ float g_v[M_ROWS * N_DIM];      // 64 MB
__device__ float g_q[M_ROWS * N_DIM];      // 64 MB
__device__ float g_coef[M_ROWS * 24];      // 1.5 MB
__device__ __nv_bfloat16 g_xhi[M_ROWS * D_DIM];    // 32 MB
__device__ __nv_bfloat16 g_xlo[M_ROWS * D_DIM];    // 32 MB
__device__ __nv_bfloat16 g_whi[3 * N_DIM * D_DIM]; // 6 MB
__device__ __nv_bfloat16 g_wlo[3 * N_DIM * D_DIM]; // 6 MB

// ---------------- fast, accurate transcendentals ---------------------------
__device__ __forceinline__ float tanh_fast(float x) {
    x = fminf(15.f, fmaxf(-15.f, x));
    float e = __expf(2.f * x);
    return __fdividef(e - 1.f, e + 1.f);
}
__device__ __forceinline__ float out_silu(float s) {
    float xs = fminf(30.f, fmaxf(-30.f, s));
    float e  = __expf(-xs);
    float sig = __fdividef(1.f, 1.f + e);
    return s * s * sig;
}

// ---------------- PTX helpers (all baseline sm_80/75 features) -------------
__device__ __forceinline__ uint32_t smem_u32(const void* p) {
    uint32_t a;
    asm("{ .reg .u64 t; cvta.to.shared.u64 t, %1; cvt.u32.u64 %0, t; }"
        : "=r"(a) : "l"(p));
    return a;
}
__device__ __forceinline__ void cp16(uint32_t s, const void* g) {
    asm volatile("cp.async.cg.shared.global [%0], [%1], 16;"
                 :: "r"(s), "l"(g) : "memory");
}
#define LDSM_X4(r0, r1, r2, r3, addr) \
    asm volatile("ldmatrix.sync.aligned.m8n8.x4.shared.b16 {%0,%1,%2,%3}, [%4];" \
        : "=r"(r0), "=r"(r1), "=r"(r2), "=r"(r3) : "r"(addr))
#define MMA_BF16(d, a, b0, b1) \
    asm volatile("mma.sync.aligned.m16n8k16.row.col.f32.bf16.bf16.f32 " \
        "{%0,%1,%2,%3},{%4,%5,%6,%7},{%8,%9},{%0,%1,%2,%3};" \
        : "+f"((d)[0]), "+f"((d)[1]), "+f"((d)[2]), "+f"((d)[3]) \
        : "r"((a)[0]), "r"((a)[1]), "r"((a)[2]), "r"((a)[3]), "r"(b0), "r"(b1))

// ============================================================================
// Conversion kernel: fp32 -> (bf16 hi, bf16 lo) for x and the three weights
// ============================================================================
__global__ __launch_bounds__(256) void convert_kernel(
    const float* __restrict__ x,  const float* __restrict__ Wk,
    const float* __restrict__ Wv, const float* __restrict__ Wq)
{
    int bid = blockIdx.x;
    const float* src;
    __nv_bfloat16 *dh, *dl;
    size_t idx;
    if (bid < 16384) {
        src = x; dh = g_xhi; dl = g_xlo;
        idx = (size_t)bid * 256 + threadIdx.x;
    } else {
        int w  = (bid - 16384) >> 10;
        int lb = (bid - 16384) & 1023;
        src = (w == 0) ? Wk : (w == 1) ? Wv : Wq;
        dh = g_whi + (size_t)w * N_DIM * D_DIM;
        dl = g_wlo + (size_t)w * N_DIM * D_DIM;
        idx = (size_t)lb * 256 + threadIdx.x;
    }
    float4 v = ((const float4*)src)[idx];
    float vv[4] = {v.x, v.y, v.z, v.w};
    __nv_bfloat16 hi[4], lo[4];
#pragma unroll
    for (int j = 0; j < 4; j++) {
        hi[j] = __float2bfloat16_rn(vv[j]);
        lo[j] = __float2bfloat16_rn(vv[j] - __bfloat162float(hi[j]));
    }
    __nv_bfloat162* dh2 = (__nv_bfloat162*)dh;
    __nv_bfloat162* dl2 = (__nv_bfloat162*)dl;
    dh2[idx * 2]     = __nv_bfloat162{hi[0], hi[1]};
    dh2[idx * 2 + 1] = __nv_bfloat162{hi[2], hi[3]};
    dl2[idx * 2]     = __nv_bfloat162{lo[0], lo[1]};
    dl2[idx * 2 + 1] = __nv_bfloat162{lo[2], lo[3]};
}

// ============================================================================
// HMMA GEMM: C[m,n] = sum_k A[m,k]*W[n,k], split-bf16 compensated (3 mma).
// CTA 128x128, 8 warps of 32(M)x64(N), K-chunks of 64, cp.async double buffer.
// Smem stage layout: Ahi @0 (16K), Alo @16K, Bhi @32K, Blo @48K.
// Rows are 64 bf16 = 128B with SW128 swizzle (conflict-free ldmatrix).
// ============================================================================
__device__ __forceinline__ void fill_stage(uint32_t st, int kb, int tid,
    const __nv_bfloat16* __restrict__ Ah, const __nv_bfloat16* __restrict__ Al,
    const __nv_bfloat16* __restrict__ Bh, const __nv_bfloat16* __restrict__ Bl)
{
#pragma unroll
    for (int v = tid; v < 1024; v += 256) {   // 128 rows x 8 chunks of 16B
        int row = v >> 3, c = v & 7;
        uint32_t so = (uint32_t)(row * 128 + ((c * 16) ^ ((row & 7) << 4)));
        size_t go = (size_t)row * D_DIM + kb + c * 8;
        cp16(st + so,         Ah + go);
        cp16(st + 16384 + so, Al + go);
        cp16(st + 32768 + so, Bh + go);
        cp16(st + 49152 + so, Bl + go);
    }
}

__global__ __launch_bounds__(256, 1) void mma_gemm_kernel()
{
    extern __shared__ char smem[];
    const uint32_t sb = smem_u32(smem);
    const int tid  = threadIdx.x;
    const int lane = tid & 31, wid = tid >> 5;
    const int wm = wid >> 1, wn = wid & 1;
    const int nt = blockIdx.x, mt = blockIdx.y, z = blockIdx.z;

    const __nv_bfloat16* Ah = g_xhi + (size_t)mt * GMT * D_DIM;
    const __nv_bfloat16* Al = g_xlo + (size_t)mt * GMT * D_DIM;
    const __nv_bfloat16* Bh = g_whi + (size_t)z * N_DIM * D_DIM + (size_t)nt * GNT * D_DIM;
    const __nv_bfloat16* Bl = g_wlo + (size_t)z * N_DIM * D_DIM + (size_t)nt * GNT * D_DIM;

    // Per-thread ldmatrix offsets
    const uint32_t aRowOff = (uint32_t)((wm * 32 + (lane & 15)) * 128);
    const uint32_t aSeg    = (uint32_t)((lane >> 4) * 16);
    const uint32_t bRowOff = (uint32_t)((wn * 64 + ((lane >> 4) << 3) + (lane & 7)) * 128);
    const uint32_t bSeg    = (uint32_t)(((lane >> 3) & 1) * 16);
    const uint32_t xorm    = (uint32_t)((lane & 7) << 4);

    float acc[2][8][4];
#pragma unroll
    for (int i = 0; i < 2; i++)
#pragma unroll
        for (int j = 0; j < 8; j++)
#pragma unroll
            for (int e = 0; e < 4; e++) acc[i][j][e] = 0.f;

    fill_stage(sb, 0, tid, Ah, Al, Bh, Bl);
    asm volatile("cp.async.commit_group;" ::: "memory");

    for (int c = 0; c < NSTEP; c++) {
        if (c + 1 < NSTEP) {
            fill_stage(sb + ((c + 1) & 1) * STAGE_BYTES, (c + 1) * KC, tid,
                       Ah, Al, Bh, Bl);
            asm volatile("cp.async.commit_group;" ::: "memory");
            asm volatile("cp.async.wait_group 1;" ::: "memory");
        } else {
            asm volatile("cp.async.wait_group 0;" ::: "memory");
        }
        __syncthreads();

        const uint32_t sA = sb + (c & 1) * STAGE_BYTES;
        const uint32_t sB = sA + 32768;

#pragma unroll
        for (int ks = 0; ks < 4; ks++) {
            const uint32_t kb = (uint32_t)(ks * 32);
            uint32_t ah[2][4], al[2][4];
#pragma unroll
            for (int i = 0; i < 2; i++) {
                uint32_t ad = sA + i * 2048 + aRowOff + ((kb + aSeg) ^ xorm);
                LDSM_X4(ah[i][0], ah[i][1], ah[i][2], ah[i][3], ad);
                LDSM_X4(al[i][0], al[i][1], al[i][2], al[i][3], ad + 16384);
            }
            uint32_t bh[8][2], bl[8][2];
#pragma unroll
            for (int jp = 0; jp < 4; jp++) {
                uint32_t bd = sB + jp * 2048 + bRowOff + ((kb + bSeg) ^ xorm);
                LDSM_X4(bh[2*jp][0], bh[2*jp][1], bh[2*jp+1][0], bh[2*jp+1][1], bd);
                LDSM_X4(bl[2*jp][0], bl[2*jp][1], bl[2*jp+1][0], bl[2*jp+1][1], bd + 16384);
            }
#pragma unroll
            for (int i = 0; i < 2; i++)
#pragma unroll
                for (int j = 0; j < 8; j++) {
                    MMA_BF16(acc[i][j], ah[i], bh[j][0], bh[j][1]);
                    MMA_BF16(acc[i][j], ah[i], bl[j][0], bl[j][1]);
                    MMA_BF16(acc[i][j], al[i], bh[j][0], bh[j][1]);
                }
        }
        __syncthreads();
    }

    // Epilogue: direct stores (C-frag: r=lane>>2, c=(lane&3)*2; +8 row pair)
    float* C = (z == 0) ? g_k : (z == 1) ? g_v : g_q;
#pragma unroll
    for (int i = 0; i < 2; i++) {
        const int r0 = mt * GMT + wm * 32 + i * 16 + (lane >> 2);
#pragma unroll
        for (int j = 0; j < 8; j++) {
            const int col = nt * GNT + wn * 64 + j * 8 + (lane & 3) * 2;
            *(float2*)&C[(size_t)r0 * N_DIM + col] =
                make_float2(acc[i][j][0], acc[i][j][1]);
            *(float2*)&C[(size_t)(r0 + 8) * N_DIM + col] =
                make_float2(acc[i][j][2], acc[i][j][3]);
        }
    }
}

// ============================================================================
// Phase B: per (t,b) coefficient reductions
// ============================================================================
__global__ __launch_bounds__(256) void coef_kernel(
    const float* __restrict__ V0, const float* __restrict__ Wkr)
{
    __shared__ float sred[8 * 25];
    __shared__ float sfin[25];

    const int b  = blockIdx.y;
    const int t0 = blockIdx.x * 16;
    const int tid = threadIdx.x;
    const int lane = tid & 31, warp = tid >> 5;

    float Vreg[4][8], Wreg[4][8];
#pragma unroll
    for (int ii = 0; ii < 4; ii++) {
        int i = tid + ii * 256;
        const float4* vp = (const float4*)&V0[(size_t)b * N_DIM * 8 + (size_t)i * 8];
        float4 v0 = vp[0], v1 = vp[1];
        Vreg[ii][0] = v0.x; Vreg[ii][1] = v0.y; Vreg[ii][2] = v0.z; Vreg[ii][3] = v0.w;
        Vreg[ii][4] = v1.x; Vreg[ii][5] = v1.y; Vreg[ii][6] = v1.z; Vreg[ii][7] = v1.w;
#pragma unroll
        for (int j = 0; j < 8; j++) Wreg[ii][j] = Wkr[j * N_DIM + i];
    }

    for (int tt = 0; tt < 16; tt++) {
        const int t = t0 + tt;
        const float* krow = &g_k[(size_t)(t * BATCH + b) * N_DIM];
        const float* qrow = &g_q[(size_t)(t * BATCH + b) * N_DIM];

        float acc[25];
#pragma unroll
        for (int c = 0; c < 25; c++) acc[c] = 0.f;

#pragma unroll
        for (int ii = 0; ii < 4; ii++) {
            int i = tid + ii * 256;
            float kv = krow[i];
            float qv = qrow[i];
            acc[24] = fmaf(kv, kv, acc[24]);
#pragma unroll
            for (int j = 0; j < 8; j++) {
                float vv = Vreg[ii][j];
                acc[j]      = fmaf(vv, kv, acc[j]);
                acc[16 + j] = fmaf(vv, qv, acc[16 + j]);
                acc[8 + j]  = fmaf(Wreg[ii][j], kv, acc[8 + j]);
            }
        }
#pragma unroll
        for (int off = 16; off > 0; off >>= 1)
#pragma unroll
            for (int c = 0; c < 25; c++)
                acc[c] += __shfl_down_sync(0xffffffffu, acc[c], off);

        if (lane == 0) {
#pragma unroll
            for (int c = 0; c < 25; c++) sred[warp * 25 + c] = acc[c];
        }
        __syncthreads();
        if (tid < 25) {
            float s = 0.f;
#pragma unroll
            for (int w = 0; w < 8; w++) s += sred[w * 25 + tid];
            sfin[tid] = s;
        }
        __syncthreads();
        if (tid < 24) {
            float scale = (tid < 16) ? (1.0f / (sqrtf(sfin[24]) + EPSV)) : 1.0f;
            g_coef[(size_t)(t * BATCH + b) * 24 + tid] = sfin[tid] * scale;
        }
        __syncthreads();
    }
}

// ============================================================================
// Phase C: register-resident scan
// ============================================================================
__global__ __launch_bounds__(256) void scan_kernel(
    const float* __restrict__ U0, float* __restrict__ out, int writeExtra)
{
    const int CH = 64;
    __shared__ float sc[CH * 24];

    const int b   = blockIdx.y;
    const int i   = blockIdx.x * 256 + threadIdx.x;
    const int tid = threadIdx.x;

    float U[8];
    {
        const float4* up = (const float4*)&U0[((size_t)b * N_DIM + i) * 8];
        float4 u0 = up[0], u1 = up[1];
        U[0]=u0.x; U[1]=u0.y; U[2]=u0.z; U[3]=u0.w;
        U[4]=u1.x; U[5]=u1.y; U[6]=u1.z; U[7]=u1.w;
    }

    float vcur = g_v[(size_t)b * N_DIM + i];

    for (int tc = 0; tc < T_STEPS; tc += CH) {
        __syncthreads();
        for (int idx = tid; idx < CH * 24; idx += 256) {
            int tt = idx / 24, c = idx - tt * 24;
            sc[idx] = g_coef[(size_t)((tc + tt) * BATCH + b) * 24 + c];
        }
        __syncthreads();

#pragma unroll 2
        for (int tt = 0; tt < CH; tt++) {
            const int t = tc + tt;
            float vnext = (t + 1 < T_STEPS)
                        ? g_v[(size_t)((t + 1) * BATCH + b) * N_DIM + i] : 0.f;
            const float* c = &sc[tt * 24];

            float ret = U[0]*c[0];
#pragma unroll
            for (int j = 1; j < 8; j++) ret = fmaf(U[j], c[j], ret);
            float delta = vcur - ret;

#pragma unroll
            for (int j = 0; j < 8; j++)
                U[j] = tanh_fast(fmaf(delta, c[8 + j], U[j]));

            float sq = U[0]*c[16];
#pragma unroll
            for (int j = 1; j < 8; j++) sq = fmaf(U[j], c[16 + j], sq);

            out[(size_t)(t * BATCH + b) * N_DIM + i] = out_silu(sq);
            vcur = vnext;
        }
    }

    if (writeExtra) {
        float* uf = out + (size_t)M_ROWS * N_DIM + ((size_t)b * N_DIM + i) * 8;
        ((float4*)uf)[0] = make_float4(U[0], U[1], U[2], U[3]);
        ((float4*)uf)[1] = make_float4(U[4], U[5], U[6], U[7]);
    }
}

// ============================================================================
extern "C" void kernel_launch(void* const* d_in, const int* in_sizes, int n_in,
                              void* d_out, int out_size)
{
    const float* x   = (const float*)d_in[0];
    const float* Wk  = (const float*)d_in[1];
    const float* Wv  = (const float*)d_in[2];
    const float* Wq  = (const float*)d_in[3];
    const float* Wkr = (const float*)d_in[4];
    const float* U0  = (const float*)d_in[5];
    const float* V0  = (const float*)d_in[6];
    float* out = (float*)d_out;

    (void)in_sizes; (void)n_in;

    cudaFuncSetAttribute(mma_gemm_kernel,
                         cudaFuncAttributeMaxDynamicSharedMemorySize, SMEM_BYTES);

    // Phase A0: bf16 hi/lo conversion
    convert_kernel<<<16384 + 3 * 1024, 256>>>(x, Wk, Wv, Wq);

    // Phase A: HMMA split-bf16 projections
    mma_gemm_kernel<<<dim3(N_DIM / GNT, M_ROWS / GMT, 3), 256, SMEM_BYTES>>>();

    // Phase B: per-(t,b) coefficient reductions
    coef_kernel<<<dim3(T_STEPS / 16, BATCH), 256>>>(V0, Wkr);

    // Phase C: register-resident scan
    const int extraElems = 2 * BATCH * N_DIM * R_DIM;
    int writeExtra = (out_size >= M_ROWS * N_DIM + extraElems) ? 1 : 0;
    scan_kernel<<<dim3(N_DIM / 256, BATCH), 256>>>(U0, out, writeExtra);

    if (writeExtra) {
        cudaMemcpyAsync(out + (size_t)M_ROWS * N_DIM + BATCH * N_DIM * R_DIM,
                        V0, (size_t)BATCH * N_DIM * R_DIM * sizeof(float),
                        cudaMemcpyDeviceToDevice, 0);
    }
}